// round 10
// baseline (speedup 1.0000x reference)
#include <cuda_runtime.h>
#include <cuda_bf16.h>
#include <cstdint>
#include <math.h>

#define BB   32
#define TT_  2048
#define CIN  80
#define HCH  256
#define KTOT 240
#define SXS  136

// scratch (device globals: no allocation allowed)
__device__ float          g_y[TT_*BB*HCH];                 // conv out (T,B,H), 64MB
__device__ unsigned short g_xk[3u*BB*256u*TT_];            // pre-shifted im2col limbs [l][b][kl(256)][t]
__device__ __align__(16) unsigned int g_wf2[98304];        // w fragment images [hh][kst16][nf16][l3][lane][r]
__device__ float  g_wt[3*CIN*HCH];                         // transposed weights [kk][c][h] (SIMT path)
__device__ double g_sum[HCH];
__device__ double g_sumsq[HCH];
__device__ float  g_mean[HCH];
__device__ float  g_rs[HCH];

typedef unsigned long long ull;

__device__ __forceinline__ uint32_t smem_u32(const void* p){
    uint32_t a; asm("{ .reg .u64 t; cvta.to.shared.u64 t, %1; cvt.u32.u64 %0, t; }" : "=r"(a) : "l"(p));
    return a;
}
__device__ __forceinline__ void lds64(uint32_t* r, uint32_t addr){
    asm volatile("ld.shared.v2.b32 {%0,%1}, [%2];" : "=r"(r[0]), "=r"(r[1]) : "r"(addr));
}
#define LDSM4T(r, a) \
    asm volatile("ldmatrix.sync.aligned.m8n8.x4.trans.shared.b16 {%0,%1,%2,%3}, [%4];" \
        : "=r"((r)[0]), "=r"((r)[1]), "=r"((r)[2]), "=r"((r)[3]) : "r"(a))
__device__ __forceinline__ void mma_bf16(float* c, const uint32_t* a, const uint32_t* b){
    asm volatile("mma.sync.aligned.m16n8k16.row.col.f32.bf16.bf16.f32 "
        "{%0,%1,%2,%3}, {%4,%5,%6,%7}, {%8,%9}, {%0,%1,%2,%3};"
        : "+f"(c[0]), "+f"(c[1]), "+f"(c[2]), "+f"(c[3])
        : "r"(a[0]), "r"(a[1]), "r"(a[2]), "r"(a[3]), "r"(b[0]), "r"(b[1]));
}
__device__ __forceinline__ void cpa16(uint32_t dst, const void* src){
    asm volatile("cp.async.cg.shared.global [%0], [%1], 16;" :: "r"(dst), "l"(src) : "memory");
}
#define CPA_COMMIT() asm volatile("cp.async.commit_group;" ::: "memory")
#define CPA_WAIT1()  asm volatile("cp.async.wait_group 1;" ::: "memory")
#define CPA_WAIT0()  asm volatile("cp.async.wait_group 0;" ::: "memory")

// SIMT helpers (R4)
__device__ __forceinline__ void fma2(ull &d, ull a, ull b){
    asm("fma.rn.f32x2 %0, %1, %2, %0;" : "+l"(d) : "l"(a), "l"(b));
}
__device__ __forceinline__ ull pack2(float x){
    ull r; asm("mov.b64 %0, {%1,%1};" : "=l"(r) : "f"(x)); return r;
}
__device__ __forceinline__ float2 unpack2(ull v){
    float2 r; asm("mov.b64 {%0,%1}, %2;" : "=f"(r.x), "=f"(r.y) : "l"(v)); return r;
}

__device__ __forceinline__ unsigned short bsplit(float x, int s){
    __nv_bfloat16 b0 = __float2bfloat16(x);
    if (s == 0) return __bfloat16_as_ushort(b0);
    float r1 = x - __bfloat162float(b0);
    __nv_bfloat16 b1 = __float2bfloat16(r1);
    if (s == 1) return __bfloat16_as_ushort(b1);
    float r2 = r1 - __bfloat162float(b1);
    return __bfloat16_as_ushort(__float2bfloat16(r2));
}

// ---------------- prep: x -> pre-shifted im2col bf16 limb tensor ----------------
__global__ void prep_x_kernel(const float* __restrict__ x){
    extern __shared__ unsigned short sl[];   // [3][80][132]
    const int b = blockIdx.y, t0 = blockIdx.x*128, tid = threadIdx.x;
    for (int i = tid; i < 131*CIN; i += 256){
        int p = i/CIN, c = i - p*CIN;
        int t = t0 - 1 + p;
        float v = (t >= 0 && t < TT_) ? x[((size_t)b*TT_ + t)*CIN + c] : 0.f;
        __nv_bfloat16 l0 = __float2bfloat16(v);
        float r1 = v - __bfloat162float(l0);
        __nv_bfloat16 l1 = __float2bfloat16(r1);
        float r2 = r1 - __bfloat162float(l1);
        __nv_bfloat16 l2 = __float2bfloat16(r2);
        sl[(0*CIN + c)*132 + p] = __bfloat16_as_ushort(l0);
        sl[(1*CIN + c)*132 + p] = __bfloat16_as_ushort(l1);
        sl[(2*CIN + c)*132 + p] = __bfloat16_as_ushort(l2);
    }
    __syncthreads();
    uint32_t* dst = (uint32_t*)g_xk;
    for (int i = tid; i < 3*256*64; i += 256){
        int j2 = i & 63, row = i >> 6;
        int l = row >> 8, klr = row & 255;
        uint32_t vv = 0;
        if (klr < KTOT){
            int c = (klr*171) >> 9, kk = klr - 3*c;
            int base = (l*CIN + c)*132 + kk;
            uint32_t v0 = sl[base + 2*j2];
            uint32_t v1 = sl[base + 2*j2 + 1];
            vv = v0 | (v1 << 16);
        }
        dst[((size_t)(l*BB + b)*256 + klr)*1024 + (t0 >> 1) + j2] = vv;
    }
}

// ---------------- prep: w -> fragment images + transposed fp32, zero BN sums ----------------
__global__ void prep_w_kernel(const float* __restrict__ w){
    int i = blockIdx.x*256 + threadIdx.x;
    if (i < HCH){ g_sum[i] = 0.0; g_sumsq[i] = 0.0; }
    if (i < 3*CIN*HCH){
        int h  = i & 255;
        int ck = i >> 8;
        int c  = ck % CIN;
        int kk = ck / CIN;
        g_wt[i] = w[h*(CIN*3) + c*3 + kk];
    }
    if (i >= 98304) return;
    int r    = i & 1;
    int lane = (i >> 1) & 31;
    int rest = i >> 6;
    int l   = rest % 3;  rest /= 3;
    int nf  = rest & 15; rest >>= 4;
    int kst = rest & 15;
    int hh  = rest >> 4;
    uint32_t vv = 0;
    if (kst < 15){
        int n  = hh*128 + nf*8 + (lane >> 2);
        int k0 = kst*16 + (lane & 3)*2 + r*8;
        int c0 = (k0*171) >> 9, kk0 = k0 - 3*c0;
        int k1 = k0 + 1;
        int c1 = (k1*171) >> 9, kk1 = k1 - 3*c1;
        uint32_t v0 = bsplit(w[(size_t)n*KTOT + c0*3 + kk0], l);
        uint32_t v1 = bsplit(w[(size_t)n*KTOT + c1*3 + kk1], l);
        vv = v0 | (v1 << 16);
    }
    g_wf2[i] = vv;
}

// ---------------- hybrid conv: MMA CTAs (h 128..255) + SIMT CTAs (h 0..127) ----------------
#define ABUF 26112u
#define BBUF 24576u
#define BBASE (2u*ABUF)
#define SMEM_HYB 104960      // max(MMA 101376, SIMT 104960)

__global__ void __launch_bounds__(256, 2) conv_hybrid_kernel(const float* __restrict__ x,
                                                             const float* __restrict__ bias){
    extern __shared__ char smem[];
    const int bid = blockIdx.x;
    const int tid = threadIdx.x;

    if (bid % 3 == 0){
        // ================= MMA path: tile 128t x 128h (h0=128), bitwise R8/R9 numerics =================
        const uint32_t sb = smem_u32(smem);
        const int id = bid / 3;              // 0..511
        const int t0 = (id & 15) << 7;
        const int b  = id >> 4;
        const int lane = tid & 31, w = tid >> 5;
        const int wm = w >> 2, wn = w & 3;   // 2m x 4n warp grid, warp tile 64x32

        float acc[4][4][4];
        #pragma unroll
        for (int mf = 0; mf < 4; ++mf)
            #pragma unroll
            for (int nf = 0; nf < 4; ++nf)
                #pragma unroll
                for (int q = 0; q < 4; ++q) acc[mf][nf][q] = 0.f;

        const uint32_t laneA = ((((lane >> 4) << 3) | (lane & 7)) * 272u)
                             + (uint32_t)(wm*64 + ((lane >> 3) & 1)*8) * 2u;

        auto prefetch = [&](int c, int buf){
            #pragma unroll
            for (int k = 0; k < 6; ++k){
                int j = tid + k*256;
                int row = j >> 4, seg = j & 15;
                int l = row >> 5, klr = row & 31;
                const char* src = (const char*)g_xk
                    + (((((size_t)l*BB + b)*256 + (c*32 + klr))*2048 + t0) << 1) + seg*16;
                cpa16(sb + (uint32_t)buf*ABUF + (uint32_t)l*8704u + (uint32_t)klr*272u + (uint32_t)seg*16u, src);
            }
            const char* bs = (const char*)g_wf2 + (size_t)(16 + c*2)*12288u;   // hh = 1
            #pragma unroll
            for (int k = 0; k < 6; ++k){
                int j = tid + k*256;
                cpa16(sb + BBASE + (uint32_t)buf*BBUF + (uint32_t)j*16u, bs + (size_t)j*16);
            }
            CPA_COMMIT();
        };

        auto kstep = [&](int ks, uint32_t aT, uint32_t bT){
            uint32_t A0[4][4], Ax[4][4], B0[4][2], Bx[4][2];
            #pragma unroll
            for (int mf = 0; mf < 4; ++mf) LDSM4T(A0[mf], aT + (uint32_t)ks*4352u + (uint32_t)mf*32u);
            #pragma unroll
            for (int nf = 0; nf < 4; ++nf) lds64(B0[nf], bT + (uint32_t)(ks*48 + nf*3)*256u);
            #pragma unroll
            for (int mf = 0; mf < 4; ++mf)
                #pragma unroll
                for (int nf = 0; nf < 4; ++nf) mma_bf16(acc[mf][nf], A0[mf], B0[nf]);   // 00
            #pragma unroll
            for (int nf = 0; nf < 4; ++nf) lds64(Bx[nf], bT + (uint32_t)(ks*48 + nf*3)*256u + 256u);
            #pragma unroll
            for (int mf = 0; mf < 4; ++mf)
                #pragma unroll
                for (int nf = 0; nf < 4; ++nf) mma_bf16(acc[mf][nf], A0[mf], Bx[nf]);   // 01
            #pragma unroll
            for (int mf = 0; mf < 4; ++mf) LDSM4T(Ax[mf], aT + (uint32_t)ks*4352u + (uint32_t)mf*32u + 8704u);
            #pragma unroll
            for (int mf = 0; mf < 4; ++mf)
                #pragma unroll
                for (int nf = 0; nf < 4; ++nf) mma_bf16(acc[mf][nf], Ax[mf], B0[nf]);   // 10
            #pragma unroll
            for (int mf = 0; mf < 4; ++mf)
                #pragma unroll
                for (int nf = 0; nf < 4; ++nf) mma_bf16(acc[mf][nf], Ax[mf], Bx[nf]);   // 11
            #pragma unroll
            for (int nf = 0; nf < 4; ++nf) lds64(Bx[nf], bT + (uint32_t)(ks*48 + nf*3)*256u + 512u);
            #pragma unroll
            for (int mf = 0; mf < 4; ++mf)
                #pragma unroll
                for (int nf = 0; nf < 4; ++nf) mma_bf16(acc[mf][nf], A0[mf], Bx[nf]);   // 02
            #pragma unroll
            for (int mf = 0; mf < 4; ++mf) LDSM4T(Ax[mf], aT + (uint32_t)ks*4352u + (uint32_t)mf*32u + 17408u);
            #pragma unroll
            for (int mf = 0; mf < 4; ++mf)
                #pragma unroll
                for (int nf = 0; nf < 4; ++nf) mma_bf16(acc[mf][nf], Ax[mf], B0[nf]);   // 20
        };

        prefetch(0, 0);
        for (int c = 0; c < 8; ++c){
            const int buf = c & 1;
            if (c < 7){ prefetch(c+1, buf^1); CPA_WAIT1(); } else { CPA_WAIT0(); }
            __syncthreads();
            const uint32_t aT = sb + (uint32_t)buf*ABUF + laneA;
            const uint32_t bT = sb + BBASE + (uint32_t)buf*BBUF + (uint32_t)(wn*4*3)*256u + (uint32_t)lane*8u;
            kstep(0, aT, bT);
            if (c < 7) kstep(1, aT, bT);
            __syncthreads();
        }

        const int rbase = t0 + wm*64;
        const int hbase = 128 + wn*32;
        #pragma unroll
        for (int mf = 0; mf < 4; ++mf){
            int m0 = rbase + mf*16 + (lane >> 2);
            #pragma unroll
            for (int nf = 0; nf < 4; ++nf){
                int n = hbase + nf*8 + (lane & 3)*2;
                float2 bv = *(const float2*)(bias + n);
                float2 o0 = make_float2(acc[mf][nf][0] + bv.x, acc[mf][nf][1] + bv.y);
                float2 o1 = make_float2(acc[mf][nf][2] + bv.x, acc[mf][nf][3] + bv.y);
                *(float2*)(g_y + ((size_t)m0*BB + b)*HCH + n)     = o0;
                *(float2*)(g_y + ((size_t)(m0+8)*BB + b)*HCH + n) = o1;
            }
        }
    } else {
        // ================= SIMT path (bitwise R4 conv), tile 128t x 64h, h < 128 =================
        float* sx = (float*)smem;                       // [CIN][SXS]
        float* sw = (float*)(smem + CIN*SXS*4);         // [3][CIN][64]
        const int id = bid - bid/3 - 1;                 // 0..1023
        const int bb = id >> 5;
        const int r  = id & 31;
        const int t0 = (r >> 1) * 128;
        const int h0 = (r & 1) * 64;

        const float* xb = x + (size_t)bb*(TT_*CIN);
        for (int i = tid; i < 130*CIN; i += 256){
            int tl = i / CIN - 1;
            int c  = i - (tl+1)*CIN;
            int gt = t0 + tl;
            float v = (gt >= 0 && gt < TT_) ? xb[(size_t)gt*CIN + c] : 0.f;
            sx[c*SXS + tl + 4] = v;
        }
        for (int i = tid; i < 3*CIN*64; i += 256){
            int hh2 = i & 63;
            int ck = i >> 6;
            sw[i] = g_wt[ck*256 + h0 + hh2];
        }
        __syncthreads();

        const int hx = tid & 15;
        const int tx = tid >> 4;
        const int tbase = tx * 8;

        ull acc[8][2];
        #pragma unroll
        for (int t = 0; t < 8; ++t){ acc[t][0] = 0ull; acc[t][1] = 0ull; }

        #pragma unroll 2
        for (int c = 0; c < CIN; ++c){
            const float4* ap = reinterpret_cast<const float4*>(sx + c*SXS + tbase);
            float4 A0 = ap[0], A1 = ap[1], A2 = ap[2], A3 = ap[3];
            float aw[16] = {A0.x,A0.y,A0.z,A0.w, A1.x,A1.y,A1.z,A1.w,
                            A2.x,A2.y,A2.z,A2.w, A3.x,A3.y,A3.z,A3.w};
            ull bw[3][2];
            #pragma unroll
            for (int kk = 0; kk < 3; ++kk){
                const ull* bp = reinterpret_cast<const ull*>(sw + (kk*CIN + c)*64 + hx*4);
                bw[kk][0] = bp[0]; bw[kk][1] = bp[1];
            }
            #pragma unroll
            for (int kk = 0; kk < 3; ++kk){
                #pragma unroll
                for (int t = 0; t < 8; ++t){
                    ull a2 = pack2(aw[t + kk + 3]);
                    fma2(acc[t][0], a2, bw[kk][0]);
                    fma2(acc[t][1], a2, bw[kk][1]);
                }
            }
        }

        float b4[4];
        #pragma unroll
        for (int j = 0; j < 4; ++j) b4[j] = bias[h0 + hx*4 + j];

        float* yout = g_y + (size_t)(t0 + tbase)*(BB*HCH) + bb*HCH + h0 + hx*4;
        #pragma unroll
        for (int t = 0; t < 8; ++t){
            float2 u0 = unpack2(acc[t][0]);
            float2 u1 = unpack2(acc[t][1]);
            float4 o = make_float4(u0.x + b4[0], u0.y + b4[1], u1.x + b4[2], u1.y + b4[3]);
            *reinterpret_cast<float4*>(yout + (size_t)t*(BB*HCH)) = o;
        }
    }
}

// ---------------- BN stats (unchanged) ----------------
__global__ void bn_stats_kernel(){
    int h = threadIdx.x;
    size_t r0 = (size_t)blockIdx.x * 128;
    const float* yp = g_y + r0*HCH + h;
    float s = 0.f, q = 0.f;
    float v[16], nx[16];
    #pragma unroll
    for (int j = 0; j < 16; ++j) v[j] = yp[(size_t)j*HCH];
    for (int ii = 0; ii < 128; ii += 16){
        if (ii < 112){
            #pragma unroll
            for (int j = 0; j < 16; ++j) nx[j] = yp[(size_t)(ii + 16 + j)*HCH];
        }
        #pragma unroll
        for (int j = 0; j < 16; ++j){ s += v[j]; q += v[j]*v[j]; }
        #pragma unroll
        for (int j = 0; j < 16; ++j) v[j] = nx[j];
    }
    atomicAdd(&g_sum[h], (double)s);
    atomicAdd(&g_sumsq[h], (double)q);
}

// ---------------- BN finalize ----------------
__global__ void finalize_kernel(){
    int h = threadIdx.x;
    const double n = (double)(TT_*BB);
    double mu  = g_sum[h] / n;
    double var = g_sumsq[h] / n - mu*mu;
    g_mean[h] = (float)mu;
    g_rs[h]   = (float)(1.0 / sqrt(var + 1e-5));
}

// ---------------- LIF recurrence (unchanged) ----------------
#define CHUNK 128
#define WARM  96
#define NCHUNK (TT_/CHUNK)
__global__ void __launch_bounds__(256) lif_kernel(const float* __restrict__ gamma,
                                                  const float* __restrict__ beta,
                                                  float* __restrict__ out){
    int g    = blockIdx.x*256 + threadIdx.x;
    int lane = g & (BB*HCH - 1);
    int chunk = g >> 13;
    int h = lane & 255;

    float mu = g_mean[h], rs = g_rs[h], ga = gamma[h], be = beta[h];
    int tstart = chunk * CHUNK;
    int tw = (chunk == 0) ? 0 : tstart - WARM;
    int tend = tstart + CHUNK;

    const float* yp = g_y + lane;
    float* op = out + lane;
    float v = 0.f;

    float cur[16], nxt[16];
    #pragma unroll
    for (int j = 0; j < 16; ++j) cur[j] = yp[(size_t)(tw + j)*(BB*HCH)];

    for (int t0v = tw; t0v < tend; t0v += 16){
        int tn = t0v + 16;
        if (tn < tend){
            #pragma unroll
            for (int j = 0; j < 16; ++j) nxt[j] = yp[(size_t)(tn + j)*(BB*HCH)];
        }
        bool do_store = (t0v >= tstart);
        #pragma unroll
        for (int j = 0; j < 16; ++j){
            float yn = fmaf((cur[j] - mu)*rs, ga, be);
            v = fmaf(v, 0.5f, yn);
            bool sp = (v >= 1.0f);
            if (do_store) op[(size_t)(t0v + j)*(BB*HCH)] = sp ? 1.0f : 0.0f;
            v = sp ? 0.0f : v;
        }
        #pragma unroll
        for (int j = 0; j < 16; ++j) cur[j] = nxt[j];
    }
}

extern "C" void kernel_launch(void* const* d_in, const int* in_sizes, int n_in,
                              void* d_out, int out_size){
    const float* x     = (const float*)d_in[0];
    const float* w     = (const float*)d_in[1];
    const float* bias  = (const float*)d_in[2];
    const float* gamma = (const float*)d_in[3];
    const float* beta  = (const float*)d_in[4];
    float* out = (float*)d_out;

    cudaFuncSetAttribute(prep_x_kernel, cudaFuncAttributeMaxDynamicSharedMemorySize, 3*CIN*132*2);
    cudaFuncSetAttribute(conv_hybrid_kernel, cudaFuncAttributeMaxDynamicSharedMemorySize, SMEM_HYB);

    prep_x_kernel<<<dim3(TT_/128, BB), 256, 3*CIN*132*2>>>(x);
    prep_w_kernel<<<384, 256>>>(w);
    conv_hybrid_kernel<<<1536, 256, SMEM_HYB>>>(x, bias);
    bn_stats_kernel<<<512, 256>>>();
    finalize_kernel<<<1, HCH>>>();
    lif_kernel<<<(BB*HCH*NCHUNK)/256, 256>>>(gamma, beta, out);
}